// round 17
// baseline (speedup 1.0000x reference)
#include <cuda_runtime.h>
#include <cuda_fp16.h>
#include <cstdint>

#define B_  256
#define T_  1024
#define H_  256

#define MT 32       // batch rows per group
#define NT 128      // permuted gate cols per CTA (32 hidden units x 4 gates)
#define NGROUP 8
#define NTILE  8
#define THREADS 320 // 8 compute warps + h-comm warp + aux warp

#define WRS 264     // Wih1 row stride (halfs) in L0's smem
#define BLKB 2560   // bytes per producer block: 32 rows x 80B (ldsm conflict-free)
#define GBUF 20480  // 8 blocks = full 32x256 A tile
#define PSLOT 16384 // partial-gates slot: 256 threads x 16 floats

// ---- dynamic smem layout (bytes) ----
#define AS_Y     0                      // L1: [3][PSLOT] partial slots (48KB)
#define AS_H     61440                  // [2][GBUF] h tiles
#define WS_OFF   102400                 // L0: [NT][WRS] halfs (Wih1)
#define BIAS_OFF 169984                 // [NT] floats
#define WX_OFF   170496                 // [NT] floats (L0)
#define MBAR_OFF 171008                 // mbarrier block
#define CRED_OFF (MBAR_OFF + 88)        // L0: credit word
#define SMEM_TOTAL 171104

// mbar byte offsets within MBAR block (8B each)
// h quarters: buf*32 + q*8  (q = producer pair {2q,2q+1} = kc 4q..4q+3)
#define MB_HTX   0
#define MB_PTX   64   // partial bulk tx: [slot] -> 64,72,80 (L1)

// -------- persistent device scratch --------
// blocked layout: [t][grp][producer][row*40 + unit] halfs (80B rows)
__device__ __align__(16) __half g_y0[T_][NGROUP][NTILE][BLKB / 2];
__device__ __align__(16) __half g_h1[2][NGROUP][NTILE][BLKB / 2];
// partial gate pre-activations (fp32 fragment layout), 3 slots
__device__ float4 g_p[3][NGROUP][NTILE][4][256];
// counting flags, 128B-strided: 256 thread-releases per step
__device__ unsigned g_flag[2][NGROUP][NTILE][32];
__device__ unsigned g_pflag[NGROUP][NTILE][32];

__global__ void init_kernel() {
    int i = threadIdx.x;
    if (i < 2 * NGROUP * NTILE) ((unsigned*)g_flag)[i * 32] = 0u;
    if (i < NGROUP * NTILE) ((unsigned*)g_pflag)[i * 32] = 0u;
}

// -------- helpers --------
__device__ __forceinline__ uint32_t smem_u32(const void* p) {
    return (uint32_t)__cvta_generic_to_shared(p);
}
__device__ __forceinline__ unsigned ld_acq(const unsigned* p) {
    unsigned v;
    asm volatile("ld.acquire.gpu.global.u32 %0, [%1];" : "=r"(v) : "l"(p) : "memory");
    return v;
}
__device__ __forceinline__ void red_add_rel(unsigned* p) {
    asm volatile("red.release.gpu.global.add.u32 [%0], 1;" :: "l"(p) : "memory");
}
__device__ __forceinline__ void st_rel_sh(uint32_t a, unsigned v) {
    asm volatile("st.release.cta.shared.u32 [%0], %1;" :: "r"(a), "r"(v) : "memory");
}
__device__ __forceinline__ unsigned ld_acq_sh(uint32_t a) {
    unsigned v;
    asm volatile("ld.acquire.cta.shared.u32 %0, [%1];" : "=r"(v) : "r"(a) : "memory");
    return v;
}
__device__ __forceinline__ float tanh_hw(float x) {
    float y;
    asm("tanh.approx.f32 %0, %1;" : "=f"(y) : "f"(x));
    return y;
}
__device__ __forceinline__ float sig_hw(float x) {
    return fmaf(0.5f, tanh_hw(0.5f * x), 0.5f);
}
__device__ __forceinline__ void mma16816(float* d, const uint32_t* a, uint32_t b0, uint32_t b1) {
    asm volatile(
        "mma.sync.aligned.m16n8k16.row.col.f32.f16.f16.f32 "
        "{%0,%1,%2,%3}, {%4,%5,%6,%7}, {%8,%9}, {%0,%1,%2,%3};\n"
        : "+f"(d[0]), "+f"(d[1]), "+f"(d[2]), "+f"(d[3])
        : "r"(a[0]), "r"(a[1]), "r"(a[2]), "r"(a[3]), "r"(b0), "r"(b1));
}
__device__ __forceinline__ void ldsm4(uint32_t* r, uint32_t addr) {
    asm volatile("ldmatrix.sync.aligned.m8n8.x4.shared.b16 {%0,%1,%2,%3}, [%4];"
        : "=r"(r[0]), "=r"(r[1]), "=r"(r[2]), "=r"(r[3]) : "r"(addr));
}
__device__ __forceinline__ void bulk_g2s(uint32_t dst, const void* src,
                                         uint32_t bytes, uint32_t mbar) {
    asm volatile(
        "cp.async.bulk.shared::cluster.global.mbarrier::complete_tx::bytes "
        "[%0], [%1], %2, [%3];"
        :: "r"(dst), "l"(src), "r"(bytes), "r"(mbar) : "memory");
}
__device__ __forceinline__ void mbar_init(uint32_t a, uint32_t cnt) {
    asm volatile("mbarrier.init.shared.b64 [%0], %1;" :: "r"(a), "r"(cnt) : "memory");
}
__device__ __forceinline__ void mbar_expect(uint32_t a, uint32_t bytes) {
    asm volatile("mbarrier.arrive.expect_tx.shared.b64 _, [%0], %1;"
                 :: "r"(a), "r"(bytes) : "memory");
}
__device__ __forceinline__ void mbar_wait(uint32_t a, uint32_t par) {
    uint32_t done = 0;
    while (!done) {
        asm volatile(
            "{\n\t.reg .pred p;\n\t"
            "mbarrier.try_wait.parity.acquire.cta.shared::cta.b64 p, [%1], %2, 0x989680;\n\t"
            "selp.b32 %0, 1, 0, p;\n\t}"
            : "=r"(done) : "r"(a), "r"(par) : "memory");
    }
}

// ====================================================================
// R16 base, rebalanced: L0 computes L1's input projection.
//  L0 step t: h-GEMM(quarters) -> epilogue -> publish h=y0[t] -> release
//             -> partial GEMM on the SAME y0[t-1] tile with Wih1 (smem)
//             -> credit-gated publish of fp32 fragments -> pflag release.
//             Tail round at t=T_ produces partial[T_-1].
//  L1 step t: wait partial slot (prefetched dist 2 by warp 9), LDS-init
//             accumulators, h-GEMM(quarters), epilogue, publish, release.
//  Bit-exact with R16's math (y-chunks then h-chunks, fp32 acc).
//  Warp 8 = h-comm (unchanged; L0 loop extended 1 iter for the tail).
//  Warp 9 = L1: partial prefetcher / L0: credit mirror of L1's hflag
//             (slot-reuse backpressure, lead cap 3).
// ====================================================================
template <bool IS_L0>
__device__ __forceinline__ void run_layer(const float* __restrict__ x,
                                          const float* __restrict__ Wih,
                                          const float* __restrict__ Whh,
                                          const float* __restrict__ bih,
                                          const float* __restrict__ bhh,
                                          const float* __restrict__ Wp,   // Wih1 (L0 only)
                                          float* __restrict__ out,
                                          int layer_idx) {
    constexpr int L = IS_L0 ? 0 : 1;

    extern __shared__ char sm[];
    const uint32_t smb = smem_u32(sm);
    float*  bias_s = (float*)(sm + BIAS_OFF);
    float*  wx_s   = (float*)(sm + WX_OFF);
    __half* Ws     = (__half*)(sm + WS_OFF);
    const uint32_t MB = smb + MBAR_OFF;
    const uint32_t CRED = smb + CRED_OFF;

    const int tid  = threadIdx.x;
    const int lane = tid & 31, warp = tid >> 5;
    const int gid  = lane >> 2, tig = lane & 3;
    const int ntile = blockIdx.x, grp = blockIdx.y;
    const int n0 = ntile * NT;
    const int b0 = grp * MT;
    const int j0 = n0 >> 2;

    // ---- mbar init + credit init ----
    if (tid == 0) {
        #pragma unroll
        for (int i = 0; i < 8; i++) mbar_init(MB + MB_HTX + i * 8, 1);
        mbar_init(MB + MB_PTX + 0, 1);
        mbar_init(MB + MB_PTX + 8, 1);
        mbar_init(MB + MB_PTX + 16, 1);
        *(volatile unsigned*)(sm + CRED_OFF) = 3u;
    }
    __syncthreads();

    // ---- one-time: bias (+ scalar input weight for L0) into smem ----
    if (tid < NT) {
        int n_g = n0 + tid;
        int p   = (n_g & 3) * H_ + (n_g >> 2);
        bias_s[tid] = bih[p] + bhh[p];
        if (IS_L0) wx_s[tid] = Wih[p];
    }

    // ---- one-time: h-half weights (Whh) into registers (compute warps) ----
    uint32_t bw[2][16][2];
    if (warp < 8) {
        #pragma unroll
        for (int ni = 0; ni < 2; ni++) {
            int n_g = n0 + warp * 16 + ni * 8 + gid;
            int p   = (n_g & 3) * H_ + (n_g >> 2);
            const float* wr = Whh + (size_t)p * H_;
            #pragma unroll
            for (int kc = 0; kc < 16; kc++) {
                int k = kc * 16 + tig * 2;
                __half2 h01 = __floats2half2_rn(wr[k], wr[k + 1]);
                __half2 h89 = __floats2half2_rn(wr[k + 8], wr[k + 9]);
                bw[ni][kc][0] = *(uint32_t*)&h01;
                bw[ni][kc][1] = *(uint32_t*)&h89;
            }
        }
    }

    if constexpr (IS_L0) {
        // Wih1 (K=256) into smem for the partial projection
        for (int idx = tid; idx < NT * H_; idx += THREADS) {
            int nl = idx >> 8, k = idx & 255;
            int n_g = n0 + nl;
            int p   = (n_g & 3) * H_ + (n_g >> 2);
            Ws[nl * WRS + k] = __float2half_rn(Wp[(size_t)p * H_ + k]);
        }
    }
    __syncthreads();

    // ---- per-lane ldsm byte offsets ----
    const uint32_t aoffB = (uint32_t)((lane & 15) * 80 + ((lane >> 4) & 1) * 16);
    uint32_t bAddr = 0;
    if constexpr (IS_L0) {
        int rB = (warp & 7) * 16 + (lane & 7) + ((lane & 16) ? 8 : 0);
        int cB = (lane & 8) ? 8 : 0;
        bAddr = smb + WS_OFF + (uint32_t)((rB * WRS + cB) * 2);
    }

    if (warp < 8) {
        // ================= COMPUTE WARPS =================
        const int r0 = gid + ((tig & 1) << 3);        // row for mi=0 (mi adds 16)
        const int u0 = (warp << 2) + (tig >> 1);      // unit for ni=0 (ni adds 2)

        float4 breg[2], wreg[2];
        #pragma unroll
        for (int ni = 0; ni < 2; ni++) {
            breg[ni] = *(const float4*)(bias_s + 4 * (u0 + 2 * ni));
            if (IS_L0) wreg[ni] = *(const float4*)(wx_s + 4 * (u0 + 2 * ni));
        }
        const float* xr[2];
        if constexpr (IS_L0) {
            xr[0] = x + (size_t)(b0 + r0) * T_;
            xr[1] = x + (size_t)(b0 + r0 + 16) * T_;
        }

        float creg[2][2] = {{0.f, 0.f}, {0.f, 0.f}};
        uint32_t phHT = 0, phP = 0;

        for (int t = 0; t < T_; ++t) {
            const int cb = t & 1, nb = cb ^ 1;
            const uint32_t hbase = smb + AS_H + (uint32_t)cb * GBUF;

            float xv[2];
            if constexpr (IS_L0) { xv[0] = xr[0][t]; xv[1] = xr[1][t]; }

            float acc[2][2][4];
            if constexpr (!IS_L0) {
                // ---- init accumulators from the prefetched partial ----
                const int ps = t % 3;
                mbar_wait(MB + MB_PTX + ps * 8, (phP >> ps) & 1u);
                phP ^= 1u << ps;
                const float4* psrc = (const float4*)(sm + AS_Y + ps * PSLOT);
                #pragma unroll
                for (int i = 0; i < 4; i++) {
                    float4 v = psrc[i * 256 + tid];
                    acc[i >> 1][i & 1][0] = v.x;
                    acc[i >> 1][i & 1][1] = v.y;
                    acc[i >> 1][i & 1][2] = v.z;
                    acc[i >> 1][i & 1][3] = v.w;
                }
            } else {
                #pragma unroll
                for (int mi = 0; mi < 2; mi++)
                    #pragma unroll
                    for (int ni = 0; ni < 2; ni++)
                        #pragma unroll
                        for (int r = 0; r < 4; r++) acc[mi][ni][r] = 0.f;
            }

            // ---- h-GEMM: 4 quarters, pipelined with producer arrival ----
            if (t > 0) {
                #pragma unroll
                for (int q = 0; q < 4; q++) {
                    const int pb = cb * 4 + q;
                    mbar_wait(MB + MB_HTX + cb * 32 + q * 8, (phHT >> pb) & 1u);
                    phHT ^= 1u << pb;
                    #pragma unroll
                    for (int kk = 0; kk < 4; kk++) {
                        const int kc = q * 4 + kk;
                        uint32_t a0[4], a1[4];
                        const uint32_t ad = hbase + (kc >> 1) * BLKB + (kc & 1) * 32 + aoffB;
                        ldsm4(a0, ad);
                        ldsm4(a1, ad + 1280);
                        mma16816(acc[0][0], a0, bw[0][kc][0], bw[0][kc][1]);
                        mma16816(acc[0][1], a0, bw[1][kc][0], bw[1][kc][1]);
                        mma16816(acc[1][0], a1, bw[0][kc][0], bw[0][kc][1]);
                        mma16816(acc[1][1], a1, bw[1][kc][0], bw[1][kc][1]);
                    }
                }
            }

            // ---- shfl epilogue ----
            #pragma unroll
            for (int mi = 0; mi < 2; mi++) {
                #pragma unroll
                for (int ni = 0; ni < 2; ni++) {
                    float sa = (tig & 1) ? acc[mi][ni][0] : acc[mi][ni][2];
                    float sb = (tig & 1) ? acc[mi][ni][1] : acc[mi][ni][3];
                    float ra = __shfl_xor_sync(0xffffffffu, sa, 1, 32);
                    float rb = __shfl_xor_sync(0xffffffffu, sb, 1, 32);
                    float pi, pf, pg, po;
                    if (tig & 1) { pi = ra;            pf = rb;
                                   pg = acc[mi][ni][2]; po = acc[mi][ni][3]; }
                    else         { pi = acc[mi][ni][0]; pf = acc[mi][ni][1];
                                   pg = ra;             po = rb; }
                    pi += breg[ni].x; pf += breg[ni].y;
                    pg += breg[ni].z; po += breg[ni].w;
                    if constexpr (IS_L0) {
                        pi += xv[mi] * wreg[ni].x;
                        pf += xv[mi] * wreg[ni].y;
                        pg += xv[mi] * wreg[ni].z;
                        po += xv[mi] * wreg[ni].w;
                    }
                    float ig = sig_hw(pi), fg = sig_hw(pf);
                    float gg = tanh_hw(pg), og = sig_hw(po);
                    float c  = fg * creg[mi][ni] + ig * gg;
                    creg[mi][ni] = c;
                    float h  = og * tanh_hw(c);

                    const int row = r0 + 16 * mi;
                    const int u   = u0 + 2 * ni;
                    __half hh = __float2half_rn(h);
                    if constexpr (IS_L0) {
                        g_y0[t][grp][ntile][row * 40 + u] = hh;
                    } else {
                        if (t + 1 < T_)
                            g_h1[nb][grp][ntile][row * 40 + u] = hh;
                    }
                    if (t == T_ - 1) {
                        size_t oidx = ((size_t)layer_idx * B_ + (b0 + row)) * H_ + j0 + u;
                        out[oidx] = h;
                        out[(size_t)2 * B_ * H_ + oidx] = c;
                    }
                }
            }

            // ---- release h (per-thread counting flag) ----
            if (IS_L0 || t + 1 < T_)
                red_add_rel(&g_flag[L][grp][ntile][0]);

            // ---- L0: partial projection of y0[t-1] for L1 (off h path) ----
            if constexpr (IS_L0) {
                if (t >= 1) {
                    float accp[2][2][4];
                    #pragma unroll
                    for (int mi = 0; mi < 2; mi++)
                        #pragma unroll
                        for (int ni = 0; ni < 2; ni++)
                            #pragma unroll
                            for (int r = 0; r < 4; r++) accp[mi][ni][r] = 0.f;
                    #pragma unroll
                    for (int kc = 0; kc < 16; kc++) {
                        uint32_t a0[4], a1[4], bb[4];
                        const uint32_t ad = hbase + (kc >> 1) * BLKB + (kc & 1) * 32 + aoffB;
                        ldsm4(a0, ad);
                        ldsm4(a1, ad + 1280);
                        ldsm4(bb, bAddr + kc * 32u);
                        mma16816(accp[0][0], a0, bb[0], bb[1]);
                        mma16816(accp[0][1], a0, bb[2], bb[3]);
                        mma16816(accp[1][0], a1, bb[0], bb[1]);
                        mma16816(accp[1][1], a1, bb[2], bb[3]);
                    }
                    // backpressure: slot (t-1)%3 overwrites partial[t-4]
                    while ((int)ld_acq_sh(CRED) < t) { }
                    float4* pd = &g_p[(t - 1) % 3][grp][ntile][0][tid];
                    #pragma unroll
                    for (int i = 0; i < 4; i++)
                        pd[i * 256] = make_float4(accp[i >> 1][i & 1][0],
                                                  accp[i >> 1][i & 1][1],
                                                  accp[i >> 1][i & 1][2],
                                                  accp[i >> 1][i & 1][3]);
                    red_add_rel(&g_pflag[grp][ntile][0]);
                }
            }
        }

        // ---- L0 tail: one extra round to produce partial[T_-1] ----
        if constexpr (IS_L0) {
            const uint32_t hb = smb + AS_H;   // buffer 0 (= T_ & 1)
            #pragma unroll
            for (int q = 0; q < 4; q++) {
                mbar_wait(MB + MB_HTX + q * 8, (phHT >> q) & 1u);
                phHT ^= 1u << q;
            }
            float accp[2][2][4];
            #pragma unroll
            for (int mi = 0; mi < 2; mi++)
                #pragma unroll
                for (int ni = 0; ni < 2; ni++)
                    #pragma unroll
                    for (int r = 0; r < 4; r++) accp[mi][ni][r] = 0.f;
            #pragma unroll
            for (int kc = 0; kc < 16; kc++) {
                uint32_t a0[4], a1[4], bb[4];
                const uint32_t ad = hb + (kc >> 1) * BLKB + (kc & 1) * 32 + aoffB;
                ldsm4(a0, ad);
                ldsm4(a1, ad + 1280);
                ldsm4(bb, bAddr + kc * 32u);
                mma16816(accp[0][0], a0, bb[0], bb[1]);
                mma16816(accp[0][1], a0, bb[2], bb[3]);
                mma16816(accp[1][0], a1, bb[0], bb[1]);
                mma16816(accp[1][1], a1, bb[2], bb[3]);
            }
            while ((int)ld_acq_sh(CRED) < T_) { }
            float4* pd = &g_p[(T_ - 1) % 3][grp][ntile][0][tid];
            #pragma unroll
            for (int i = 0; i < 4; i++)
                pd[i * 256] = make_float4(accp[i >> 1][i & 1][0],
                                          accp[i >> 1][i & 1][1],
                                          accp[i >> 1][i & 1][2],
                                          accp[i >> 1][i & 1][3]);
            red_add_rel(&g_pflag[grp][ntile][0]);
        }
    } else if (warp == 8) {
        // ================= H-COMM WARP =================
        const int tmax = IS_L0 ? T_ : (T_ - 1);   // L0: extra iter for the tail
        for (int t = 0; t < tmax; ++t) {
            const int nb = (t + 1) & 1;

            if (lane == 0) {
                #pragma unroll
                for (int q = 0; q < 4; q++)
                    mbar_expect(MB + MB_HTX + nb * 32 + q * 8, 2 * BLKB);
            }
            __syncwarp();

            if (lane < 8) {
                while (ld_acq(&g_flag[L][grp][lane][0]) <
                       (unsigned)((t + 1) << 8)) { }
                const void* src = IS_L0 ? (const void*)&g_y0[t][grp][lane][0]
                                        : (const void*)&g_h1[nb][grp][lane][0];
                bulk_g2s(smb + AS_H + (uint32_t)nb * GBUF + lane * BLKB, src,
                         BLKB, MB + MB_HTX + nb * 32 + (lane >> 1) * 8);
            }
            __syncwarp();
        }
    } else {
        // ================= AUX WARP =================
        if constexpr (IS_L0) {
            // credit mirror: credit = (L1 hflag steps) + 3
            if (lane == 0) {
                for (;;) {
                    unsigned v = ld_acq(&g_flag[1][grp][ntile][0]);
                    unsigned c = (v >> 8) + 3u;
                    st_rel_sh(CRED, c);
                    if (c >= (unsigned)T_) break;
                }
            }
        } else {
            // partial prefetcher (distance 2, 3 slots)
            if (lane == 0) {
                mbar_expect(MB + MB_PTX + 0, PSLOT);
                while (ld_acq(&g_pflag[grp][ntile][0]) < (1u << 8)) { }
                bulk_g2s(smb + AS_Y + 0, &g_p[0][grp][ntile][0][0],
                         PSLOT, MB + MB_PTX + 0);
                mbar_expect(MB + MB_PTX + 8, PSLOT);
                while (ld_acq(&g_pflag[grp][ntile][0]) < (2u << 8)) { }
                bulk_g2s(smb + AS_Y + PSLOT, &g_p[1][grp][ntile][0][0],
                         PSLOT, MB + MB_PTX + 8);
                for (int s = 0; s + 2 < T_; ++s) {
                    const int slot = (s + 2) % 3;
                    if (s > 0) {   // slot-reuse: own compute passed step s-1
                        while (ld_acq(&g_flag[1][grp][ntile][0]) <
                               (unsigned)(s << 8)) { }
                    }
                    mbar_expect(MB + MB_PTX + slot * 8, PSLOT);
                    while (ld_acq(&g_pflag[grp][ntile][0]) <
                           (unsigned)((s + 3) << 8)) { }
                    bulk_g2s(smb + AS_Y + (uint32_t)slot * PSLOT,
                             &g_p[slot][grp][ntile][0][0],
                             PSLOT, MB + MB_PTX + slot * 8);
                }
            }
        }
    }
}

__global__ void __launch_bounds__(THREADS, 1)
lstm_fused_kernel(const float* __restrict__ x,
                  const float* __restrict__ Wih0, const float* __restrict__ Whh0,
                  const float* __restrict__ bih0, const float* __restrict__ bhh0,
                  const float* __restrict__ Wih1, const float* __restrict__ Whh1,
                  const float* __restrict__ bih1, const float* __restrict__ bhh1,
                  float* __restrict__ out) {
    if (blockIdx.z == 0)
        run_layer<true >(x, Wih0, Whh0, bih0, bhh0, Wih1, out, 0);
    else
        run_layer<false>(nullptr, Wih1, Whh1, bih1, bhh1, nullptr, out, 1);
}

extern "C" void kernel_launch(void* const* d_in, const int* in_sizes, int n_in,
                              void* d_out, int out_size) {
    (void)in_sizes; (void)n_in; (void)out_size;
    const float* x    = (const float*)d_in[0];
    const float* Wih0 = (const float*)d_in[1];
    const float* Whh0 = (const float*)d_in[2];
    const float* bih0 = (const float*)d_in[3];
    const float* bhh0 = (const float*)d_in[4];
    const float* Wih1 = (const float*)d_in[5];
    const float* Whh1 = (const float*)d_in[6];
    const float* bih1 = (const float*)d_in[7];
    const float* bhh1 = (const float*)d_in[8];
    float* out = (float*)d_out;

    cudaFuncSetAttribute((const void*)&lstm_fused_kernel,
                         cudaFuncAttributeMaxDynamicSharedMemorySize, SMEM_TOTAL);

    init_kernel<<<1, 256>>>();

    dim3 grid(NTILE, NGROUP, 2);
    lstm_fused_kernel<<<grid, THREADS, SMEM_TOTAL>>>(
        x, Wih0, Whh0, bih0, bhh0, Wih1, Whh1, bih1, bhh1, out);
}